// round 10
// baseline (speedup 1.0000x reference)
#include <cuda_runtime.h>
#include <cuda_bf16.h>
#include <cstdint>

#define NF    100000
#define CLIP  50
#define D     64
#define NT    13   // friend-slot iterations (4 friends each; 52 slots, 2 padded)
#define DEPTH 5    // cp.async pipeline depth (committed groups in flight)

__device__ __forceinline__ void cp16(uint32_t smem_addr, const void* gptr) {
    asm volatile("cp.async.ca.shared.global [%0], [%1], 16;"
                 :: "r"(smem_addr), "l"(gptr));
}
__device__ __forceinline__ void cp_commit() {
    asm volatile("cp.async.commit_group;");
}
__device__ __forceinline__ void cp_wait() {
    asm volatile("cp.async.wait_group %0;" :: "n"(DEPTH - 1));
}

// 8 lanes per friend, 4 friends per warp-iteration, 13 iterations.
// logits = sum_c gate_c * pd_c / nfr  (pd_c = dot(fe_c, ie*w) = pre-sigmoid value)
// Gathers staged through per-warp SMEM ring via cp.async: deep MLP at low regcount.
__global__ __launch_bounds__(256, 5)
void gmf_kernel(const int*   __restrict__ user_indices,
                const int*   __restrict__ item_indices,
                const int*   __restrict__ ufi,          // [100000, 50]
                const float* __restrict__ emb_user,     // [100001, 64] (row NF == 0)
                const float* __restrict__ emb_item,     // [100000, 64]
                const float* __restrict__ affine_w,     // [64]
                const float* __restrict__ affine_b,     // scalar
                float*       __restrict__ rating_out,   // [B]
                float*       __restrict__ gidx_out,     // [B, 50] or null
                int B)
{
    // [warpInBlock][slot][friendGrp][16 x float4 = 256 B row]
    __shared__ float4 sbuf[8][DEPTH][4][16];

    const int warp = (int)((blockIdx.x * blockDim.x + threadIdx.x) >> 5);
    const int lane = threadIdx.x & 31;
    if (warp >= B) return;

    const int wib = (int)(threadIdx.x >> 5);   // warp in block
    const int lig = lane & 7;                  // lane in 8-lane group
    const int grp = lane >> 3;                 // friend-group 0..3

    const int   u    = user_indices[warp];
    const int   it   = item_indices[warp];
    const float bias = *affine_b;

    // lane holds dims [4*lig, 4*lig+4) and [32+4*lig, ...) of item*w
    float4 iw_lo, iw_hi;
    {
        const float4* ie = (const float4*)(emb_item + (size_t)it * D);
        const float4* w  = (const float4*)affine_w;
        float4 a = ie[lig],     b0 = w[lig];
        float4 c = ie[lig + 8], d0 = w[lig + 8];
        iw_lo = make_float4(a.x*b0.x, a.y*b0.y, a.z*b0.z, a.w*b0.w);
        iw_hi = make_float4(c.x*d0.x, c.y*d0.y, c.z*d0.z, c.w*d0.w);
    }

    const int* friends = ufi + (size_t)u * CLIP;

    // preload friend ids (uniform per 8-lane group; L1/L2 resident)
    int fid[NT];
    #pragma unroll
    for (int t = 0; t < NT; ++t) {
        const int c = 4 * t + grp;
        fid[t] = (c < CLIP) ? friends[c] : NF;
    }

    // ---- prologue: stage iterations 0..DEPTH-1
    #pragma unroll
    for (int t = 0; t < DEPTH; ++t) {
        const float4* src = (const float4*)(emb_user + (size_t)fid[t] * D);
        float4* dst = &sbuf[wib][t][grp][0];
        cp16((uint32_t)__cvta_generic_to_shared(dst + lig),     src + lig);
        cp16((uint32_t)__cvta_generic_to_shared(dst + lig + 8), src + lig + 8);
        cp_commit();
    }

    float s   = 0.f;             // sum of gate*pd (uniform within 8-lane group)
    int   nfr = 0;
    float ga = 0.f, gb = 0.f;    // gate stash: t==lig, t==lig+8

    #pragma unroll
    for (int t = 0; t < NT; ++t) {
        cp_wait();               // group t complete -> slot t%DEPTH valid

        const int slot = t % DEPTH;
        const float4 f_lo = sbuf[wib][slot][grp][lig];      // lane reads its own 16 B
        const float4 f_hi = sbuf[wib][slot][grp][lig + 8];

        // refill this slot for iteration t+DEPTH (async write lands >=250cyc later,
        // long after the 29-cyc LDS above has returned)
        if (t + DEPTH < NT) {
            const float4* src = (const float4*)(emb_user + (size_t)fid[t + DEPTH] * D);
            float4* dst = &sbuf[wib][slot][grp][0];
            cp16((uint32_t)__cvta_generic_to_shared(dst + lig),     src + lig);
            cp16((uint32_t)__cvta_generic_to_shared(dst + lig + 8), src + lig + 8);
        }
        cp_commit();             // commit every iteration (possibly empty group)

        float pd = f_lo.x*iw_lo.x + f_lo.y*iw_lo.y + f_lo.z*iw_lo.z + f_lo.w*iw_lo.w
                 + f_hi.x*iw_hi.x + f_hi.y*iw_hi.y + f_hi.z*iw_hi.z + f_hi.w*iw_hi.w;
        pd += __shfl_xor_sync(0xffffffffu, pd, 4);
        pd += __shfl_xor_sync(0xffffffffu, pd, 2);
        pd += __shfl_xor_sync(0xffffffffu, pd, 1);

        const float gate = 1.f / (1.f + __expf(-(pd + bias)));

        s   += gate * pd;            // padded slots: pd==0 -> contributes 0
        nfr += (fid[t] != NF);

        if (t == lig)     ga = gate;   // covers t=0..7
        if (t == lig + 8) gb = gate;   // covers t=8..12
    }

    // ---- gate output: gp[4*t + grp], coalesced across the warp ----
    if (gidx_out) {
        float* gp = gidx_out + (size_t)warp * CLIP;
        gp[4 * lig + grp] = ga;                          // slots 0..31
        const int c2 = 32 + 4 * lig + grp;               // slots 32..49 (+2 padded)
        if (c2 < CLIP) gp[c2] = gb;
    }

    // ---- combine the 4 groups (values uniform within each group) ----
    s   += __shfl_xor_sync(0xffffffffu, s, 8);
    s   += __shfl_xor_sync(0xffffffffu, s, 16);
    nfr += __shfl_xor_sync(0xffffffffu, nfr, 8);
    nfr += __shfl_xor_sync(0xffffffffu, nfr, 16);

    if (lane == 0) {
        const float logit = s / (float)nfr + bias;   // nfr==0 -> inf/nan, matches ref
        rating_out[warp] = 1.f / (1.f + __expf(-logit));
    }
}

extern "C" void kernel_launch(void* const* d_in, const int* in_sizes, int n_in,
                              void* d_out, int out_size)
{
    const int*   user_indices = (const int*)  d_in[0];
    const int*   item_indices = (const int*)  d_in[1];
    const int*   ufi          = (const int*)  d_in[2];
    const float* emb_user     = (const float*)d_in[3];
    const float* emb_item     = (const float*)d_in[4];
    const float* affine_w     = (const float*)d_in[5];
    const float* affine_b     = (const float*)d_in[6];

    const int B = in_sizes[0];
    float* out = (float*)d_out;

    float* rating = out;
    float* gidx   = (out_size >= B * (1 + CLIP)) ? (out + B) : nullptr;

    const int threads = 256;                 // 8 warps/block, 1 warp per batch row
    const int blocks  = (B * 32 + threads - 1) / threads;
    gmf_kernel<<<blocks, threads>>>(user_indices, item_indices, ufi,
                                    emb_user, emb_item, affine_w, affine_b,
                                    rating, gidx, B);
}

// round 11
// speedup vs baseline: 1.2655x; 1.2655x over previous
#include <cuda_runtime.h>
#include <cuda_bf16.h>

#define NF   100000
#define CLIP 50
#define D    64
#define NT   13   // friend-slot iterations (4 friends each; 52 slots, 2 padded)
#define PF   4    // software-pipeline depth

// 8 lanes per friend, 4 friends per warp-iteration, 13 iterations.
// logits = sum_c gate_c * pd_c / nfr  (pd_c = dot(fe_c, ie*w) = pre-sigmoid value)
// Rolling 4-entry fid queue instead of a 13-entry array: PF=4 pipeline at <=64 regs
// -> 4 CTAs/SM resident, ~256 gather lines in flight per SM.
__global__ __launch_bounds__(256, 4)
void gmf_kernel(const int*   __restrict__ user_indices,
                const int*   __restrict__ item_indices,
                const int*   __restrict__ ufi,          // [100000, 50]
                const float* __restrict__ emb_user,     // [100001, 64] (row NF == 0)
                const float* __restrict__ emb_item,     // [100000, 64]
                const float* __restrict__ affine_w,     // [64]
                const float* __restrict__ affine_b,     // scalar
                float*       __restrict__ rating_out,   // [B]
                float*       __restrict__ gidx_out,     // [B, 50] or null
                int B)
{
    const int warp = (int)((blockIdx.x * blockDim.x + threadIdx.x) >> 5);
    const int lane = threadIdx.x & 31;
    if (warp >= B) return;

    const int lig = lane & 7;    // lane in 8-lane group
    const int grp = lane >> 3;   // friend-group 0..3

    const int   u    = user_indices[warp];
    const int   it   = item_indices[warp];
    const float bias = *affine_b;

    // lane holds dims [4*lig, 4*lig+4) and [32+4*lig, ...) of item*w
    float4 iw_lo, iw_hi;
    {
        const float4* ie = (const float4*)(emb_item + (size_t)it * D);
        const float4* w  = (const float4*)affine_w;
        float4 a = ie[lig],     b0 = w[lig];
        float4 c = ie[lig + 8], d0 = w[lig + 8];
        iw_lo = make_float4(a.x*b0.x, a.y*b0.y, a.z*b0.z, a.w*b0.w);
        iw_hi = make_float4(c.x*d0.x, c.y*d0.y, c.z*d0.z, c.w*d0.w);
    }

    const int* friends = ufi + (size_t)u * CLIP;   // 200 B row, L1-resident after 1st touch

    float4 blo[PF], bhi[PF];     // pipeline data buffers (compile-time indexed)
    int    fq [PF];              // rolling fid queue (compile-time indexed)

    // ---- prologue: fids + loads for t = 0..PF-1
    #pragma unroll
    for (int t = 0; t < PF; ++t) {
        fq[t] = friends[4 * t + grp];              // slots 0..15 all < CLIP
        const float4* fr = (const float4*)(emb_user + (size_t)fq[t] * D);
        blo[t] = fr[lig];
        bhi[t] = fr[lig + 8];
    }

    float s   = 0.f;             // sum of gate*pd (uniform within 8-lane group)
    int   nfr = 0;
    float ga = 0.f, gb = 0.f;    // gate stash: t==lig, t==lig+8

    // ---- steady state: consume slot, refill fid+data for t+PF
    #pragma unroll
    for (int t = 0; t < NT; ++t) {
        const int slot = t % PF;
        const float4 f_lo = blo[slot];
        const float4 f_hi = bhi[slot];
        const int    myfid = fq[slot];

        if (t + PF < NT) {
            const int c = 4 * (t + PF) + grp;               // slot 16..51
            const int nf = (c < CLIP) ? friends[c] : NF;    // L1 hit
            fq[slot] = nf;
            const float4* fr = (const float4*)(emb_user + (size_t)nf * D);
            blo[slot] = fr[lig];
            bhi[slot] = fr[lig + 8];
        }

        float pd = f_lo.x*iw_lo.x + f_lo.y*iw_lo.y + f_lo.z*iw_lo.z + f_lo.w*iw_lo.w
                 + f_hi.x*iw_hi.x + f_hi.y*iw_hi.y + f_hi.z*iw_hi.z + f_hi.w*iw_hi.w;
        pd += __shfl_xor_sync(0xffffffffu, pd, 4);
        pd += __shfl_xor_sync(0xffffffffu, pd, 2);
        pd += __shfl_xor_sync(0xffffffffu, pd, 1);

        const float gate = 1.f / (1.f + __expf(-(pd + bias)));

        s   += gate * pd;            // padded slots: pd==0 -> contributes 0
        nfr += (myfid != NF);

        if (t == lig)     ga = gate;   // covers t=0..7
        if (t == lig + 8) gb = gate;   // covers t=8..12
    }

    // ---- gate output: gp[4*t + grp], coalesced across the warp ----
    if (gidx_out) {
        float* gp = gidx_out + (size_t)warp * CLIP;
        gp[4 * lig + grp] = ga;                          // slots 0..31
        const int c2 = 32 + 4 * lig + grp;               // slots 32..49 (+2 padded)
        if (c2 < CLIP) gp[c2] = gb;
    }

    // ---- combine the 4 groups (values uniform within each group) ----
    s   += __shfl_xor_sync(0xffffffffu, s, 8);
    s   += __shfl_xor_sync(0xffffffffu, s, 16);
    nfr += __shfl_xor_sync(0xffffffffu, nfr, 8);
    nfr += __shfl_xor_sync(0xffffffffu, nfr, 16);

    if (lane == 0) {
        const float logit = s / (float)nfr + bias;   // nfr==0 -> inf/nan, matches ref
        rating_out[warp] = 1.f / (1.f + __expf(-logit));
    }
}

extern "C" void kernel_launch(void* const* d_in, const int* in_sizes, int n_in,
                              void* d_out, int out_size)
{
    const int*   user_indices = (const int*)  d_in[0];
    const int*   item_indices = (const int*)  d_in[1];
    const int*   ufi          = (const int*)  d_in[2];
    const float* emb_user     = (const float*)d_in[3];
    const float* emb_item     = (const float*)d_in[4];
    const float* affine_w     = (const float*)d_in[5];
    const float* affine_b     = (const float*)d_in[6];

    const int B = in_sizes[0];
    float* out = (float*)d_out;

    float* rating = out;
    float* gidx   = (out_size >= B * (1 + CLIP)) ? (out + B) : nullptr;

    const int threads = 256;                 // 8 warps/block, 1 warp per batch row
    const int blocks  = (B * 32 + threads - 1) / threads;
    gmf_kernel<<<blocks, threads>>>(user_indices, item_indices, ufi,
                                    emb_user, emb_item, affine_w, affine_b,
                                    rating, gidx, B);
}

// round 12
// speedup vs baseline: 1.2778x; 1.0097x over previous
#include <cuda_runtime.h>
#include <cuda_bf16.h>
#include <cstdint>

#define NF   100000
#define CLIP 50
#define D    64
#define NT   13   // friend-slot iterations (4 friends each; 52 slots, 2 padded)
#define PF   4    // software-pipeline depth

// float4 gather with L2 evict_last policy (keeps emb_user table L2-resident)
__device__ __forceinline__ float4 ldg_pol(const float4* p, uint64_t pol) {
    float4 v;
    asm volatile("ld.global.L2::cache_hint.v4.f32 {%0,%1,%2,%3}, [%4], %5;"
                 : "=f"(v.x), "=f"(v.y), "=f"(v.z), "=f"(v.w)
                 : "l"(p), "l"(pol));
    return v;
}
// streaming store: outputs are write-once, never re-read -> don't pollute L2
__device__ __forceinline__ void stg_cs(float* p, float v) {
    asm volatile("st.global.cs.f32 [%0], %1;" :: "l"(p), "f"(v));
}

// 8 lanes per friend, 4 friends per warp-iteration, 13 iterations.
// logits = sum_c gate_c * pd_c / nfr  (pd_c = dot(fe_c, ie*w) is the pre-sigmoid value)
__global__ __launch_bounds__(256, 3)
void gmf_kernel(const int*   __restrict__ user_indices,
                const int*   __restrict__ item_indices,
                const int*   __restrict__ ufi,          // [100000, 50]
                const float* __restrict__ emb_user,     // [100001, 64] (row NF == 0)
                const float* __restrict__ emb_item,     // [100000, 64]
                const float* __restrict__ affine_w,     // [64]
                const float* __restrict__ affine_b,     // scalar
                float*       __restrict__ rating_out,   // [B]
                float*       __restrict__ gidx_out,     // [B, 50] or null
                int B)
{
    const int warp = (int)((blockIdx.x * blockDim.x + threadIdx.x) >> 5);
    const int lane = threadIdx.x & 31;
    if (warp >= B) return;

    const int lig = lane & 7;    // lane in 8-lane group
    const int grp = lane >> 3;   // friend-group 0..3

    uint64_t pol;
    asm volatile("createpolicy.fractional.L2::evict_last.b64 %0, 1.0;" : "=l"(pol));

    const int   u    = user_indices[warp];
    const int   it   = item_indices[warp];
    const float bias = *affine_b;

    // lane holds dims [4*lig, 4*lig+4) and [32+4*lig, ...) of item*w
    float4 iw_lo, iw_hi;
    {
        const float4* ie = (const float4*)(emb_item + (size_t)it * D);
        const float4* w  = (const float4*)affine_w;
        float4 a = ie[lig],     b0 = w[lig];
        float4 c = ie[lig + 8], d0 = w[lig + 8];
        iw_lo = make_float4(a.x*b0.x, a.y*b0.y, a.z*b0.z, a.w*b0.w);
        iw_hi = make_float4(c.x*d0.x, c.y*d0.y, c.z*d0.z, c.w*d0.w);
    }

    const int* friends = ufi + (size_t)u * CLIP;

    // preload friend ids (uniform per 8-lane group; L1/L2 resident)
    int fid[NT];
    #pragma unroll
    for (int t = 0; t < NT; ++t) {
        const int c = 4 * t + grp;
        fid[t] = (c < CLIP) ? friends[c] : NF;
    }

    float4 blo[PF], bhi[PF];     // pipeline buffers (compile-time indexed)

    // ---- prologue: issue loads for t = 0..PF-1
    #pragma unroll
    for (int t = 0; t < PF; ++t) {
        const float4* fr = (const float4*)(emb_user + (size_t)fid[t] * D);
        blo[t] = ldg_pol(fr + lig,     pol);
        bhi[t] = ldg_pol(fr + lig + 8, pol);
    }

    float s   = 0.f;             // sum of gate*pd (uniform within 8-lane group)
    int   nfr = 0;
    float ga = 0.f, gb = 0.f;    // gate stash: t==lig, t==lig+8

    // ---- steady state: prefetch t+PF, compute t
    #pragma unroll
    for (int t = 0; t < NT; ++t) {
        const int slot = t % PF;
        const float4 f_lo = blo[slot];
        const float4 f_hi = bhi[slot];

        if (t + PF < NT) {
            const float4* fr = (const float4*)(emb_user + (size_t)fid[t + PF] * D);
            blo[slot] = ldg_pol(fr + lig,     pol);
            bhi[slot] = ldg_pol(fr + lig + 8, pol);
        }

        float pd = f_lo.x*iw_lo.x + f_lo.y*iw_lo.y + f_lo.z*iw_lo.z + f_lo.w*iw_lo.w
                 + f_hi.x*iw_hi.x + f_hi.y*iw_hi.y + f_hi.z*iw_hi.z + f_hi.w*iw_hi.w;
        pd += __shfl_xor_sync(0xffffffffu, pd, 4);
        pd += __shfl_xor_sync(0xffffffffu, pd, 2);
        pd += __shfl_xor_sync(0xffffffffu, pd, 1);

        const float gate = 1.f / (1.f + __expf(-(pd + bias)));

        s   += gate * pd;            // padded slots: pd==0 -> contributes 0
        nfr += (fid[t] != NF);

        if (t == lig)     ga = gate;   // covers t=0..7
        if (t == lig + 8) gb = gate;   // covers t=8..12
    }

    // ---- gate output: gp[4*t + grp], coalesced, streaming ----
    if (gidx_out) {
        float* gp = gidx_out + (size_t)warp * CLIP;
        stg_cs(gp + 4 * lig + grp, ga);                  // slots 0..31
        const int c2 = 32 + 4 * lig + grp;               // slots 32..49 (+2 padded)
        if (c2 < CLIP) stg_cs(gp + c2, gb);
    }

    // ---- combine the 4 groups (values uniform within each group) ----
    s   += __shfl_xor_sync(0xffffffffu, s, 8);
    s   += __shfl_xor_sync(0xffffffffu, s, 16);
    nfr += __shfl_xor_sync(0xffffffffu, nfr, 8);
    nfr += __shfl_xor_sync(0xffffffffu, nfr, 16);

    if (lane == 0) {
        const float logit = s / (float)nfr + bias;   // nfr==0 -> inf/nan, matches ref
        stg_cs(rating_out + warp, 1.f / (1.f + __expf(-logit)));
    }
}

extern "C" void kernel_launch(void* const* d_in, const int* in_sizes, int n_in,
                              void* d_out, int out_size)
{
    const int*   user_indices = (const int*)  d_in[0];
    const int*   item_indices = (const int*)  d_in[1];
    const int*   ufi          = (const int*)  d_in[2];
    const float* emb_user     = (const float*)d_in[3];
    const float* emb_item     = (const float*)d_in[4];
    const float* affine_w     = (const float*)d_in[5];
    const float* affine_b     = (const float*)d_in[6];

    const int B = in_sizes[0];
    float* out = (float*)d_out;

    float* rating = out;
    float* gidx   = (out_size >= B * (1 + CLIP)) ? (out + B) : nullptr;

    const int threads = 256;                 // 8 warps/block, 1 warp per batch row
    const int blocks  = (B * 32 + threads - 1) / threads;
    gmf_kernel<<<blocks, threads>>>(user_indices, item_indices, ufi,
                                    emb_user, emb_item, affine_w, affine_b,
                                    rating, gidx, B);
}